// round 5
// baseline (speedup 1.0000x reference)
#include <cuda_runtime.h>
#include <cstdint>

#define N_NODES 16384
#define HDIM    64
#define MAXN    160          // max nnz/row: Binomial(16384,0.004)+1, mean 66, ~11 sigma headroom
#define NBLK    1024         // gemm blocks (16 rows each)
#define BN_EPS  1e-5f
#define NSLICE  6            // scan row-slices (puts a scan slice at ncu launch #6)

// ---------------- device scratch (no allocations allowed) ----------------
__device__ int   g_idx[N_NODES * MAXN];     // CSR-ish column indices per row
__device__ int   g_nnz[N_NODES];            // row degree (= row sum of adj)
__device__ float g_pooled[N_NODES * HDIM];
__device__ float g_t[N_NODES * HDIM];
__device__ float g_t2[N_NODES * HDIM];
__device__ float g_part[NBLK * 128];        // per-block [sum(64) | sumsq(64)]
__device__ float g_ab[128];                 // BN affine: a[64], b[64]

// ---------------- K1: stream adj (row slice), build index lists + degrees ----------------
__global__ __launch_bounds__(256) void scan_adj(const float* __restrict__ adj,
                                                int row0, int row1) {
    int lane   = threadIdx.x & 31;
    int wlocal = threadIdx.x >> 5;
    int row    = row0 + (blockIdx.x << 3) + wlocal;

    __shared__ int snnz[8];
    if (lane == 0) snnz[wlocal] = 0;
    __syncwarp();
    if (row >= row1) return;

    const uint4* base = reinterpret_cast<const uint4*>(adj + (size_t)row * N_NODES);
    int* rowidx = g_idx + (size_t)row * MAXN;

    #pragma unroll 4
    for (int t = 0; t < 64; t++) {
        int f4 = t * 64 + lane * 2;                 // warp covers 1KB contiguous
        uint4 a = __ldcs(base + f4);                // streaming: evict-first
        uint4 b = __ldcs(base + f4 + 1);
        unsigned m = (a.x | a.y | a.z | a.w) | (b.x | b.y | b.z | b.w);
        if (m) {
            unsigned w[8] = {a.x, a.y, a.z, a.w, b.x, b.y, b.z, b.w};
            int col0 = f4 * 4;
            int loc[8];
            int cnt = 0;
            #pragma unroll
            for (int k = 0; k < 8; k++)
                if (w[k]) loc[cnt++] = col0 + k;
            int pos = atomicAdd(&snnz[wlocal], cnt);
            if (pos + cnt <= MAXN) {
                for (int i = 0; i < cnt; i++) rowidx[pos + i] = loc[i];
            }
        }
    }
    __syncwarp();
    if (lane == 0) g_nnz[row] = snnz[wlocal];
}

// ---------------- K2: sparse mean aggregation (4 rows per 256-thread block) ----------------
// out[r,:] = mean_{j in nbr(r)} f(src[j,:]);  f = identity (APPLY=0) or
// relu(a*x+b) using g_ab (APPLY=1, fuses previous layer's outer BN+ReLU).
template <int APPLY>
__global__ __launch_bounds__(256) void agg(const float* __restrict__ src,
                                           float* __restrict__ out) {
    int rl = threadIdx.x >> 6;              // 0..3 row within block
    int c  = threadIdx.x & 63;              // column
    int r  = (blockIdx.x << 2) + rl;

    __shared__ int ids[4][MAXN];
    int nnz = g_nnz[r];
    for (int i = c; i < nnz; i += 64) ids[rl][i] = g_idx[(size_t)r * MAXN + i];
    __syncthreads();

    float bn_a = 0.f, bn_b = 0.f;
    if (APPLY) { bn_a = g_ab[c]; bn_b = g_ab[64 + c]; }

    // 8-way unroll: 8 independent loads in flight (hide L2 latency)
    float a0 = 0.f, a1 = 0.f, a2 = 0.f, a3 = 0.f;
    int k = 0;
    for (; k + 8 <= nnz; k += 8) {
        float v0 = src[(size_t)ids[rl][k]     * HDIM + c];
        float v1 = src[(size_t)ids[rl][k + 1] * HDIM + c];
        float v2 = src[(size_t)ids[rl][k + 2] * HDIM + c];
        float v3 = src[(size_t)ids[rl][k + 3] * HDIM + c];
        float v4 = src[(size_t)ids[rl][k + 4] * HDIM + c];
        float v5 = src[(size_t)ids[rl][k + 5] * HDIM + c];
        float v6 = src[(size_t)ids[rl][k + 6] * HDIM + c];
        float v7 = src[(size_t)ids[rl][k + 7] * HDIM + c];
        if (APPLY) {
            v0 = fmaxf(fmaf(bn_a, v0, bn_b), 0.f);
            v1 = fmaxf(fmaf(bn_a, v1, bn_b), 0.f);
            v2 = fmaxf(fmaf(bn_a, v2, bn_b), 0.f);
            v3 = fmaxf(fmaf(bn_a, v3, bn_b), 0.f);
            v4 = fmaxf(fmaf(bn_a, v4, bn_b), 0.f);
            v5 = fmaxf(fmaf(bn_a, v5, bn_b), 0.f);
            v6 = fmaxf(fmaf(bn_a, v6, bn_b), 0.f);
            v7 = fmaxf(fmaf(bn_a, v7, bn_b), 0.f);
        }
        a0 += v0 + v4; a1 += v1 + v5; a2 += v2 + v6; a3 += v3 + v7;
    }
    for (; k < nnz; k++) {
        float v = src[(size_t)ids[rl][k] * HDIM + c];
        if (APPLY) v = fmaxf(fmaf(bn_a, v, bn_b), 0.f);
        a0 += v;
    }
    out[(size_t)r * HDIM + c] = ((a0 + a1) + (a2 + a3)) / (float)nnz;
}

// ---------------- K3: fused GEMM [16384,64]@[64,64] + bias + BN-stat partials
// MODE==1 applies relu(a*x+b) (previous inner BN) to the input tile.
template <int MODE>
__global__ __launch_bounds__(256) void gemm64(const float* __restrict__ in,
                                              const float* __restrict__ W,
                                              const float* __restrict__ bias,
                                              float* __restrict__ out,
                                              float* __restrict__ part) {
    __shared__ float Ws[64 * 64];
    __shared__ float Is[16][68];            // padded vs bank conflicts

    int tid = threadIdx.x;
    for (int i = tid; i < 4096; i += 256) Ws[i] = W[i];

    int row0 = blockIdx.x * 16;
    for (int i = tid; i < 1024; i += 256) {
        int rr = i >> 6, cc = i & 63;
        float v = in[(size_t)(row0 + rr) * HDIM + cc];
        if (MODE == 1)
            v = fmaxf(fmaf(g_ab[cc], v, g_ab[64 + cc]), 0.f);
        Is[rr][cc] = v;
    }
    __syncthreads();

    int ty = tid >> 4;          // output row within tile
    int tx = tid & 15;          // 4-col group
    float acc[4];
    #pragma unroll
    for (int j = 0; j < 4; j++) acc[j] = bias[tx * 4 + j];

    #pragma unroll
    for (int k = 0; k < 64; k++) {
        float iv = Is[ty][k];
        #pragma unroll
        for (int j = 0; j < 4; j++)
            acc[j] = fmaf(iv, Ws[k * 64 + tx * 4 + j], acc[j]);
    }

    size_t obase = (size_t)(row0 + ty) * HDIM + tx * 4;
    #pragma unroll
    for (int j = 0; j < 4; j++) out[obase + j] = acc[j];

    // per-block column stats (sum, sumsq) -> g_part (deterministic, no atomics)
    __syncthreads();
    #pragma unroll
    for (int j = 0; j < 4; j++) Is[ty][tx * 4 + j] = acc[j];
    __syncthreads();
    if (tid < 64) {
        float s = 0.f;
        #pragma unroll
        for (int r = 0; r < 16; r++) s += Is[r][tid];
        part[(size_t)blockIdx.x * 128 + tid] = s;
    }
    __syncthreads();
    #pragma unroll
    for (int j = 0; j < 4; j++) Is[ty][tx * 4 + j] = acc[j] * acc[j];
    __syncthreads();
    if (tid < 64) {
        float s = 0.f;
        #pragma unroll
        for (int r = 0; r < 16; r++) s += Is[r][tid];
        part[(size_t)blockIdx.x * 128 + 64 + tid] = s;
    }
}

// ---------------- K4: reduce partials -> BN affine coefficients ----------------
// grid=64 (one block per column), 256 threads stride the 1024 gemm blocks.
__global__ __launch_bounds__(256) void bn_finalize(const float* __restrict__ g,
                                                   const float* __restrict__ be) {
    int c = blockIdx.x;                      // column 0..63
    int t = threadIdx.x;

    float s = 0.f, q = 0.f;
    #pragma unroll 4
    for (int b = t; b < NBLK; b += 256) {
        s += g_part[(size_t)b * 128 + c];
        q += g_part[(size_t)b * 128 + 64 + c];
    }
    __shared__ float ss[256];
    __shared__ float qq[256];
    ss[t] = s; qq[t] = q;
    __syncthreads();
    #pragma unroll
    for (int o = 128; o > 0; o >>= 1) {
        if (t < o) { ss[t] += ss[t + o]; qq[t] += qq[t + o]; }
        __syncthreads();
    }
    if (t == 0) {
        const float invn = 1.0f / (float)N_NODES;
        float mean = ss[0] * invn;
        float var  = qq[0] * invn - mean * mean;
        float a = g[c] * rsqrtf(var + BN_EPS);
        g_ab[c]      = a;
        g_ab[64 + c] = be[c] - mean * a;
    }
}

// ---------------- K5: elementwise h = relu(a*t2 + b) (final layer only) ----------------
__global__ __launch_bounds__(256) void apply_bn_relu(const float* __restrict__ t2,
                                                     float* __restrict__ h) {
    int i = blockIdx.x * 256 + threadIdx.x;
    int c = i & 63;
    h[i] = fmaxf(fmaf(g_ab[c], t2[i], g_ab[64 + c]), 0.f);
}

// ---------------- K6: pooled_h = graph_pool @ h  (general dense, zero-skip) ----------------
__global__ __launch_bounds__(256) void pool(const float* __restrict__ gp,
                                            const float* __restrict__ h,
                                            float* __restrict__ out) {
    int g = blockIdx.x;                 // 128 graphs
    int c    = threadIdx.x & 63;
    int lane = threadIdx.x >> 6;        // 4 node-lanes (warp-uniform)
    const float* gprow = gp + (size_t)g * N_NODES;

    float acc = 0.f;
    for (int n0 = lane; n0 < N_NODES; n0 += 32) {
        #pragma unroll
        for (int u = 0; u < 8; u++) {
            int n = n0 + u * 4;
            float w = __ldcs(gprow + n);
            if (w != 0.f) acc = fmaf(w, h[(size_t)n * HDIM + c], acc);
        }
    }
    __shared__ float red[4][64];
    red[lane][c] = acc;
    __syncthreads();
    if (threadIdx.x < 64)
        out[(size_t)g * HDIM + threadIdx.x] =
            (red[0][threadIdx.x] + red[1][threadIdx.x]) +
            (red[2][threadIdx.x] + red[3][threadIdx.x]);
}

// ---------------- launch ----------------
extern "C" void kernel_launch(void* const* d_in, const int* in_sizes, int n_in,
                              void* d_out, int out_size) {
    const float* x   = (const float*)d_in[0];
    const float* adj = (const float*)d_in[1];
    const float* gp  = (const float*)d_in[2];

    const float* P[16];
    for (int i = 0; i < 16; i++) P[i] = (const float*)d_in[3 + i];

    float* out      = (float*)d_out;
    float* h_nodes  = out + 128 * HDIM;   // [16384,64] after the [128,64] readout

    float *pooled, *t, *t2, *part;
    cudaGetSymbolAddress((void**)&pooled, g_pooled);
    cudaGetSymbolAddress((void**)&t,      g_t);
    cudaGetSymbolAddress((void**)&t2,     g_t2);
    cudaGetSymbolAddress((void**)&part,   g_part);

    // 1) one pass over adj -> CSR indices + degrees, in NSLICE row-slices.
    // Slice #6 lands in the fixed ncu -s 5 -c 1 capture window -> direct
    // measurement of the scan's per-byte cost.
    {
        const int per = (N_NODES + NSLICE - 1) / NSLICE;   // 2731
        for (int s = 0; s < NSLICE; s++) {
            int r0 = s * per;
            int r1 = (r0 + per < N_NODES) ? (r0 + per) : N_NODES;
            int blocks = (r1 - r0 + 7) / 8;
            scan_adj<<<blocks, 256>>>(adj, r0, r1);
        }
    }

    // ---- layer 0 ----
    agg<0><<<N_NODES / 4, 256>>>(x, pooled);
    gemm64<0><<<NBLK, 256>>>(pooled, P[0], P[1], t, part);
    bn_finalize<<<64, 256>>>(P[2], P[3]);               // g1_0, be1_0
    gemm64<1><<<NBLK, 256>>>(t, P[4], P[5], t2, part);
    bn_finalize<<<64, 256>>>(P[6], P[7]);               // g_0, be_0

    // ---- layer 1 (outer BN+ReLU of layer 0 fused into the gather) ----
    agg<1><<<N_NODES / 4, 256>>>(t2, pooled);
    gemm64<0><<<NBLK, 256>>>(pooled, P[8], P[9], t, part);
    bn_finalize<<<64, 256>>>(P[10], P[11]);             // g1_1, be1_1
    gemm64<1><<<NBLK, 256>>>(t, P[12], P[13], t2, part);
    bn_finalize<<<64, 256>>>(P[14], P[15]);             // g_1, be_1
    apply_bn_relu<<<(N_NODES * HDIM) / 256, 256>>>(t2, h_nodes);

    // ---- graph readout ----
    pool<<<128, 256>>>(gp, h_nodes, out);

    (void)in_sizes; (void)n_in; (void)out_size;
}

// round 6
// speedup vs baseline: 1.2426x; 1.2426x over previous
#include <cuda_runtime.h>
#include <cstdint>

#define N_NODES 16384
#define HDIM    64
#define MAXN    160          // max nnz/row: Binomial(16384,0.004)+1, mean 66, ~11 sigma headroom
#define NBLK    1024         // gemm blocks (16 rows each)
#define BN_EPS  1e-5f
#define AGG_SLICES 5         // agg<0> slices (puts an agg slice at ncu launch #6)

// ---------------- device scratch (no allocations allowed) ----------------
__device__ int   g_idx[N_NODES * MAXN];     // CSR-ish column indices per row
__device__ int   g_nnz[N_NODES];            // row degree (= row sum of adj)
__device__ __align__(16) float g_pooled[N_NODES * HDIM];
__device__ __align__(16) float g_t[N_NODES * HDIM];
__device__ __align__(16) float g_t2[N_NODES * HDIM];
__device__ __align__(16) float g_part[NBLK * 128];   // per-block [sum(64) | sumsq(64)]
__device__ __align__(16) float g_ab[128];            // BN affine: a[64], b[64]

// ---------------- K1: stream adj once (full grid), build index lists + degrees ----------------
__global__ __launch_bounds__(256) void scan_adj(const float* __restrict__ adj) {
    int lane   = threadIdx.x & 31;
    int wlocal = threadIdx.x >> 5;
    int row    = (blockIdx.x << 3) + wlocal;        // 2048 blocks * 8 warps

    __shared__ int snnz[8];
    if (lane == 0) snnz[wlocal] = 0;
    __syncwarp();

    const uint4* base = reinterpret_cast<const uint4*>(adj + (size_t)row * N_NODES);
    int* rowidx = g_idx + (size_t)row * MAXN;

    #pragma unroll 4
    for (int t = 0; t < 64; t++) {
        int f4 = t * 64 + lane * 2;                 // warp covers 1KB contiguous
        uint4 a = __ldcs(base + f4);                // streaming: evict-first
        uint4 b = __ldcs(base + f4 + 1);
        unsigned m = (a.x | a.y | a.z | a.w) | (b.x | b.y | b.z | b.w);
        if (m) {
            unsigned w[8] = {a.x, a.y, a.z, a.w, b.x, b.y, b.z, b.w};
            int col0 = f4 * 4;
            int loc[8];
            int cnt = 0;
            #pragma unroll
            for (int k = 0; k < 8; k++)
                if (w[k]) loc[cnt++] = col0 + k;
            int pos = atomicAdd(&snnz[wlocal], cnt);
            if (pos + cnt <= MAXN) {
                for (int i = 0; i < cnt; i++) rowidx[pos + i] = loc[i];
            }
        }
    }
    __syncwarp();
    if (lane == 0) g_nnz[row] = snnz[wlocal];
}

// ---------------- K2: sparse mean aggregation, float4 gather ----------------
// 256 threads = 4 rows; per row, 64 threads = 4 neighbor-groups x 16 lanes x float4.
// Group g sums neighbors k ≡ g (mod 4); cross-group reduce in smem.
// APPLY=1 fuses relu(a*x+b) (previous layer's outer BN+ReLU) into the gather.
template <int APPLY>
__global__ __launch_bounds__(256) void agg(const float* __restrict__ src,
                                           float* __restrict__ out, int blk0) {
    int bid = blk0 + blockIdx.x;
    int rl  = threadIdx.x >> 6;             // 0..3 row within block
    int t6  = threadIdx.x & 63;
    int grp = t6 >> 4;                      // 0..3 neighbor group
    int cg  = t6 & 15;                      // column group (4 floats)
    int r   = (bid << 2) + rl;

    __shared__ int    ids[4][MAXN];
    __shared__ float4 red[4][4][16];        // [rl][grp][cg]

    int nnz = g_nnz[r];
    for (int i = t6; i < nnz; i += 64) ids[rl][i] = g_idx[(size_t)r * MAXN + i];
    __syncthreads();

    float4 bna, bnb;
    if (APPLY) {
        bna = *reinterpret_cast<const float4*>(&g_ab[cg * 4]);
        bnb = *reinterpret_cast<const float4*>(&g_ab[64 + cg * 4]);
    }

    float4 acc = make_float4(0.f, 0.f, 0.f, 0.f);
    int k = grp;
    for (; k + 4 < nnz; k += 8) {           // 2 loads in flight per thread
        float4 v0 = *reinterpret_cast<const float4*>(src + (size_t)ids[rl][k]     * HDIM + cg * 4);
        float4 v1 = *reinterpret_cast<const float4*>(src + (size_t)ids[rl][k + 4] * HDIM + cg * 4);
        if (APPLY) {
            v0.x = fmaxf(fmaf(bna.x, v0.x, bnb.x), 0.f);
            v0.y = fmaxf(fmaf(bna.y, v0.y, bnb.y), 0.f);
            v0.z = fmaxf(fmaf(bna.z, v0.z, bnb.z), 0.f);
            v0.w = fmaxf(fmaf(bna.w, v0.w, bnb.w), 0.f);
            v1.x = fmaxf(fmaf(bna.x, v1.x, bnb.x), 0.f);
            v1.y = fmaxf(fmaf(bna.y, v1.y, bnb.y), 0.f);
            v1.z = fmaxf(fmaf(bna.z, v1.z, bnb.z), 0.f);
            v1.w = fmaxf(fmaf(bna.w, v1.w, bnb.w), 0.f);
        }
        acc.x += v0.x + v1.x; acc.y += v0.y + v1.y;
        acc.z += v0.z + v1.z; acc.w += v0.w + v1.w;
    }
    if (k < nnz) {
        float4 v0 = *reinterpret_cast<const float4*>(src + (size_t)ids[rl][k] * HDIM + cg * 4);
        if (APPLY) {
            v0.x = fmaxf(fmaf(bna.x, v0.x, bnb.x), 0.f);
            v0.y = fmaxf(fmaf(bna.y, v0.y, bnb.y), 0.f);
            v0.z = fmaxf(fmaf(bna.z, v0.z, bnb.z), 0.f);
            v0.w = fmaxf(fmaf(bna.w, v0.w, bnb.w), 0.f);
        }
        acc.x += v0.x; acc.y += v0.y; acc.z += v0.z; acc.w += v0.w;
    }

    red[rl][grp][cg] = acc;
    __syncthreads();

    // 64 threads per row finalize one column each
    int col = t6;
    const float* r0 = reinterpret_cast<const float*>(&red[rl][0][col >> 2]);
    const float* r1 = reinterpret_cast<const float*>(&red[rl][1][col >> 2]);
    const float* r2 = reinterpret_cast<const float*>(&red[rl][2][col >> 2]);
    const float* r3 = reinterpret_cast<const float*>(&red[rl][3][col >> 2]);
    int comp = col & 3;
    float s = (r0[comp] + r1[comp]) + (r2[comp] + r3[comp]);
    out[(size_t)r * HDIM + col] = s / (float)nnz;
}

// ---------------- K3: fused GEMM [16384,64]@[64,64] + bias + BN-stat partials
// MODE==1 applies relu(a*x+b) (previous inner BN) to the input tile.
template <int MODE>
__global__ __launch_bounds__(256) void gemm64(const float* __restrict__ in,
                                              const float* __restrict__ W,
                                              const float* __restrict__ bias,
                                              float* __restrict__ out,
                                              float* __restrict__ part) {
    __shared__ float Ws[64 * 64];
    __shared__ float Is[16][68];            // padded vs bank conflicts

    int tid = threadIdx.x;
    for (int i = tid; i < 4096; i += 256) Ws[i] = W[i];

    int row0 = blockIdx.x * 16;
    for (int i = tid; i < 1024; i += 256) {
        int rr = i >> 6, cc = i & 63;
        float v = in[(size_t)(row0 + rr) * HDIM + cc];
        if (MODE == 1)
            v = fmaxf(fmaf(g_ab[cc], v, g_ab[64 + cc]), 0.f);
        Is[rr][cc] = v;
    }
    __syncthreads();

    int ty = tid >> 4;          // output row within tile
    int tx = tid & 15;          // 4-col group
    float acc[4];
    #pragma unroll
    for (int j = 0; j < 4; j++) acc[j] = bias[tx * 4 + j];

    #pragma unroll
    for (int k = 0; k < 64; k++) {
        float iv = Is[ty][k];
        #pragma unroll
        for (int j = 0; j < 4; j++)
            acc[j] = fmaf(iv, Ws[k * 64 + tx * 4 + j], acc[j]);
    }

    size_t obase = (size_t)(row0 + ty) * HDIM + tx * 4;
    #pragma unroll
    for (int j = 0; j < 4; j++) out[obase + j] = acc[j];

    // per-block column stats (sum, sumsq) -> g_part (deterministic, no atomics)
    __syncthreads();
    #pragma unroll
    for (int j = 0; j < 4; j++) Is[ty][tx * 4 + j] = acc[j];
    __syncthreads();
    if (tid < 64) {
        float s = 0.f;
        #pragma unroll
        for (int r = 0; r < 16; r++) s += Is[r][tid];
        part[(size_t)blockIdx.x * 128 + tid] = s;
    }
    __syncthreads();
    #pragma unroll
    for (int j = 0; j < 4; j++) Is[ty][tx * 4 + j] = acc[j] * acc[j];
    __syncthreads();
    if (tid < 64) {
        float s = 0.f;
        #pragma unroll
        for (int r = 0; r < 16; r++) s += Is[r][tid];
        part[(size_t)blockIdx.x * 128 + 64 + tid] = s;
    }
}

// ---------------- K4: reduce partials -> BN affine coefficients ----------------
__global__ __launch_bounds__(256) void bn_finalize(const float* __restrict__ g,
                                                   const float* __restrict__ be) {
    int c = blockIdx.x;                      // column 0..63
    int t = threadIdx.x;

    float s = 0.f, q = 0.f;
    #pragma unroll 4
    for (int b = t; b < NBLK; b += 256) {
        s += g_part[(size_t)b * 128 + c];
        q += g_part[(size_t)b * 128 + 64 + c];
    }
    __shared__ float ss[256];
    __shared__ float qq[256];
    ss[t] = s; qq[t] = q;
    __syncthreads();
    #pragma unroll
    for (int o = 128; o > 0; o >>= 1) {
        if (t < o) { ss[t] += ss[t + o]; qq[t] += qq[t + o]; }
        __syncthreads();
    }
    if (t == 0) {
        const float invn = 1.0f / (float)N_NODES;
        float mean = ss[0] * invn;
        float var  = qq[0] * invn - mean * mean;
        float a = g[c] * rsqrtf(var + BN_EPS);
        g_ab[c]      = a;
        g_ab[64 + c] = be[c] - mean * a;
    }
}

// ---------------- K5: elementwise h = relu(a*t2 + b) (final layer only) ----------------
__global__ __launch_bounds__(256) void apply_bn_relu(const float* __restrict__ t2,
                                                     float* __restrict__ h) {
    int i = blockIdx.x * 256 + threadIdx.x;
    int c = i & 63;
    h[i] = fmaxf(fmaf(g_ab[c], t2[i], g_ab[64 + c]), 0.f);
}

// ---------------- K6: pooled_h = graph_pool @ h  (general dense, zero-skip) ----------------
__global__ __launch_bounds__(256) void pool(const float* __restrict__ gp,
                                            const float* __restrict__ h,
                                            float* __restrict__ out) {
    int g = blockIdx.x;                 // 128 graphs
    int c    = threadIdx.x & 63;
    int lane = threadIdx.x >> 6;        // 4 node-lanes (warp-uniform)
    const float* gprow = gp + (size_t)g * N_NODES;

    float acc = 0.f;
    for (int n0 = lane; n0 < N_NODES; n0 += 32) {
        #pragma unroll
        for (int u = 0; u < 8; u++) {
            int n = n0 + u * 4;
            float w = __ldcs(gprow + n);
            if (w != 0.f) acc = fmaf(w, h[(size_t)n * HDIM + c], acc);
        }
    }
    __shared__ float red[4][64];
    red[lane][c] = acc;
    __syncthreads();
    if (threadIdx.x < 64)
        out[(size_t)g * HDIM + threadIdx.x] =
            (red[0][threadIdx.x] + red[1][threadIdx.x]) +
            (red[2][threadIdx.x] + red[3][threadIdx.x]);
}

// ---------------- launch ----------------
extern "C" void kernel_launch(void* const* d_in, const int* in_sizes, int n_in,
                              void* d_out, int out_size) {
    const float* x   = (const float*)d_in[0];
    const float* adj = (const float*)d_in[1];
    const float* gp  = (const float*)d_in[2];

    const float* P[16];
    for (int i = 0; i < 16; i++) P[i] = (const float*)d_in[3 + i];

    float* out      = (float*)d_out;
    float* h_nodes  = out + 128 * HDIM;   // [16384,64] after the [128,64] readout

    float *pooled, *t, *t2, *part;
    cudaGetSymbolAddress((void**)&pooled, g_pooled);
    cudaGetSymbolAddress((void**)&t,      g_t);
    cudaGetSymbolAddress((void**)&t2,     g_t2);
    cudaGetSymbolAddress((void**)&part,   g_part);

    // 1) one full-grid pass over adj -> CSR indices + degrees
    scan_adj<<<2048, 256>>>(adj);

    // ---- layer 0 ----
    // agg<0> sliced into AGG_SLICES launches (~820 blocks each, still near-full
    // SM fill). Launch #6 overall = last agg slice -> direct agg measurement
    // in the fixed ncu -s 5 -c 1 window.
    {
        const int total_blocks = N_NODES / 4;                 // 4096
        const int per = (total_blocks + AGG_SLICES - 1) / AGG_SLICES;  // 820
        for (int s = 0; s < AGG_SLICES; s++) {
            int b0 = s * per;
            int nb = (b0 + per <= total_blocks) ? per : (total_blocks - b0);
            agg<0><<<nb, 256>>>(x, pooled, b0);
        }
    }
    gemm64<0><<<NBLK, 256>>>(pooled, P[0], P[1], t, part);
    bn_finalize<<<64, 256>>>(P[2], P[3]);               // g1_0, be1_0
    gemm64<1><<<NBLK, 256>>>(t, P[4], P[5], t2, part);
    bn_finalize<<<64, 256>>>(P[6], P[7]);               // g_0, be_0

    // ---- layer 1 (outer BN+ReLU of layer 0 fused into the gather) ----
    agg<1><<<N_NODES / 4, 256>>>(t2, pooled, 0);
    gemm64<0><<<NBLK, 256>>>(pooled, P[8], P[9], t, part);
    bn_finalize<<<64, 256>>>(P[10], P[11]);             // g1_1, be1_1
    gemm64<1><<<NBLK, 256>>>(t, P[12], P[13], t2, part);
    bn_finalize<<<64, 256>>>(P[14], P[15]);             // g_1, be_1
    apply_bn_relu<<<(N_NODES * HDIM) / 256, 256>>>(t2, h_nodes);

    // ---- graph readout ----
    pool<<<128, 256>>>(gp, h_nodes, out);

    (void)in_sizes; (void)n_in; (void)out_size;
}

// round 7
// speedup vs baseline: 1.2943x; 1.0416x over previous
#include <cuda_runtime.h>
#include <cstdint>

#define N_NODES 16384
#define HDIM    64
#define MAXN    160          // max nnz/row: Binomial(16384,0.004)+1, mean 66, ~11 sigma headroom
#define NBLK    1024         // gemm blocks (16 rows each)
#define BN_EPS  1e-5f

// ---------------- device scratch (no allocations allowed) ----------------
__device__ int   g_idx[N_NODES * MAXN];     // CSR-ish column indices per row
__device__ int   g_nnz[N_NODES];            // row degree (= row sum of adj)
__device__ __align__(16) float g_pooled[N_NODES * HDIM];
__device__ __align__(16) float g_t[N_NODES * HDIM];
__device__ __align__(16) float g_t2[N_NODES * HDIM];
__device__ __align__(16) float g_part[NBLK * 128];   // per-block [sum(64) | sumsq(64)]
__device__ __align__(16) float g_ab[128];            // BN affine: a[64], b[64]

// ---------------- K1: fused adj scan + layer-0 mean aggregation ----------------
// One warp per row. Phase 1: stream the 64KB row, compact nonzero column ids
// into SMEM (+ mirror to g_idx for layer 1). Phase 2: gather x[j,:] over the
// id list (ids already SMEM-resident) and write pooled[r,:] = mean. The phase-2
// L2 gather overlaps other warps' DRAM streaming.
__global__ __launch_bounds__(256) void scan_agg(const float* __restrict__ adj,
                                                const float* __restrict__ x,
                                                float* __restrict__ pooled) {
    int lane   = threadIdx.x & 31;
    int wlocal = threadIdx.x >> 5;
    int row    = (blockIdx.x << 3) + wlocal;        // 2048 blocks * 8 warps

    __shared__ int snnz[8];
    __shared__ int ids[8][MAXN];
    if (lane == 0) snnz[wlocal] = 0;
    __syncwarp();

    const uint4* base = reinterpret_cast<const uint4*>(adj + (size_t)row * N_NODES);
    int* rowidx = g_idx + (size_t)row * MAXN;

    // ---- phase 1: stream + compact ----
    #pragma unroll 4
    for (int t = 0; t < 64; t++) {
        int f4 = t * 64 + lane * 2;                 // warp covers 1KB contiguous
        uint4 a = __ldcs(base + f4);                // streaming: evict-first
        uint4 b = __ldcs(base + f4 + 1);
        unsigned m = (a.x | a.y | a.z | a.w) | (b.x | b.y | b.z | b.w);
        if (m) {
            unsigned w[8] = {a.x, a.y, a.z, a.w, b.x, b.y, b.z, b.w};
            int col0 = f4 * 4;
            int loc[8];
            int cnt = 0;
            #pragma unroll
            for (int k = 0; k < 8; k++)
                if (w[k]) loc[cnt++] = col0 + k;
            int pos = atomicAdd(&snnz[wlocal], cnt);
            if (pos + cnt <= MAXN) {
                for (int i = 0; i < cnt; i++) {
                    ids[wlocal][pos + i] = loc[i];
                    rowidx[pos + i]      = loc[i];
                }
            }
        }
    }
    __syncwarp();
    int nnz = snnz[wlocal];
    if (lane == 0) g_nnz[row] = nnz;

    // ---- phase 2: gather x over the id list -> pooled[row,:] ----
    // half-warps take alternating list positions; 16 lanes x float4 = 64 cols.
    int half = lane >> 4;                   // 0/1
    int cg   = lane & 15;                   // column group (4 floats)
    float4 acc = make_float4(0.f, 0.f, 0.f, 0.f);

    int k = half;
    for (; k + 2 < nnz; k += 4) {           // 2 float4 loads in flight
        int i0 = ids[wlocal][k];
        int i1 = ids[wlocal][k + 2];
        float4 v0 = *reinterpret_cast<const float4*>(x + (size_t)i0 * HDIM + cg * 4);
        float4 v1 = *reinterpret_cast<const float4*>(x + (size_t)i1 * HDIM + cg * 4);
        acc.x += v0.x + v1.x; acc.y += v0.y + v1.y;
        acc.z += v0.z + v1.z; acc.w += v0.w + v1.w;
    }
    if (k < nnz) {
        int i0 = ids[wlocal][k];
        float4 v0 = *reinterpret_cast<const float4*>(x + (size_t)i0 * HDIM + cg * 4);
        acc.x += v0.x; acc.y += v0.y; acc.z += v0.z; acc.w += v0.w;
    }
    // combine the two halves
    acc.x += __shfl_down_sync(0xffffffffu, acc.x, 16);
    acc.y += __shfl_down_sync(0xffffffffu, acc.y, 16);
    acc.z += __shfl_down_sync(0xffffffffu, acc.z, 16);
    acc.w += __shfl_down_sync(0xffffffffu, acc.w, 16);
    if (half == 0) {
        float inv = 1.0f / (float)nnz;
        float4 r = make_float4(acc.x * inv, acc.y * inv, acc.z * inv, acc.w * inv);
        *reinterpret_cast<float4*>(pooled + (size_t)row * HDIM + cg * 4) = r;
    }
}

// ---------------- K2: sparse mean aggregation, float4 gather, MLP=4 ----------------
// 256 threads = 4 rows; per row, 64 threads = 4 neighbor-groups x 16 lanes x float4.
// APPLY=1 fuses relu(a*x+b) (previous layer's outer BN+ReLU) into the gather.
template <int APPLY>
__global__ __launch_bounds__(256) void agg(const float* __restrict__ src,
                                           float* __restrict__ out) {
    int rl  = threadIdx.x >> 6;             // 0..3 row within block
    int t6  = threadIdx.x & 63;
    int grp = t6 >> 4;                      // 0..3 neighbor group
    int cg  = t6 & 15;                      // column group (4 floats)
    int r   = ((int)blockIdx.x << 2) + rl;

    __shared__ int    ids[4][MAXN];
    __shared__ float4 red[4][4][16];        // [rl][grp][cg]

    int nnz = g_nnz[r];
    for (int i = t6; i < nnz; i += 64) ids[rl][i] = g_idx[(size_t)r * MAXN + i];
    __syncthreads();

    float4 bna, bnb;
    if (APPLY) {
        bna = *reinterpret_cast<const float4*>(&g_ab[cg * 4]);
        bnb = *reinterpret_cast<const float4*>(&g_ab[64 + cg * 4]);
    }

    float4 acc = make_float4(0.f, 0.f, 0.f, 0.f);
    int k = grp;
    for (; k + 12 < nnz; k += 16) {         // 4 loads in flight per thread
        int i0 = ids[rl][k];
        int i1 = ids[rl][k + 4];
        int i2 = ids[rl][k + 8];
        int i3 = ids[rl][k + 12];
        float4 v0 = *reinterpret_cast<const float4*>(src + (size_t)i0 * HDIM + cg * 4);
        float4 v1 = *reinterpret_cast<const float4*>(src + (size_t)i1 * HDIM + cg * 4);
        float4 v2 = *reinterpret_cast<const float4*>(src + (size_t)i2 * HDIM + cg * 4);
        float4 v3 = *reinterpret_cast<const float4*>(src + (size_t)i3 * HDIM + cg * 4);
        if (APPLY) {
            v0.x = fmaxf(fmaf(bna.x, v0.x, bnb.x), 0.f);
            v0.y = fmaxf(fmaf(bna.y, v0.y, bnb.y), 0.f);
            v0.z = fmaxf(fmaf(bna.z, v0.z, bnb.z), 0.f);
            v0.w = fmaxf(fmaf(bna.w, v0.w, bnb.w), 0.f);
            v1.x = fmaxf(fmaf(bna.x, v1.x, bnb.x), 0.f);
            v1.y = fmaxf(fmaf(bna.y, v1.y, bnb.y), 0.f);
            v1.z = fmaxf(fmaf(bna.z, v1.z, bnb.z), 0.f);
            v1.w = fmaxf(fmaf(bna.w, v1.w, bnb.w), 0.f);
            v2.x = fmaxf(fmaf(bna.x, v2.x, bnb.x), 0.f);
            v2.y = fmaxf(fmaf(bna.y, v2.y, bnb.y), 0.f);
            v2.z = fmaxf(fmaf(bna.z, v2.z, bnb.z), 0.f);
            v2.w = fmaxf(fmaf(bna.w, v2.w, bnb.w), 0.f);
            v3.x = fmaxf(fmaf(bna.x, v3.x, bnb.x), 0.f);
            v3.y = fmaxf(fmaf(bna.y, v3.y, bnb.y), 0.f);
            v3.z = fmaxf(fmaf(bna.z, v3.z, bnb.z), 0.f);
            v3.w = fmaxf(fmaf(bna.w, v3.w, bnb.w), 0.f);
        }
        acc.x += (v0.x + v1.x) + (v2.x + v3.x);
        acc.y += (v0.y + v1.y) + (v2.y + v3.y);
        acc.z += (v0.z + v1.z) + (v2.z + v3.z);
        acc.w += (v0.w + v1.w) + (v2.w + v3.w);
    }
    for (; k < nnz; k += 4) {
        int i0 = ids[rl][k];
        float4 v0 = *reinterpret_cast<const float4*>(src + (size_t)i0 * HDIM + cg * 4);
        if (APPLY) {
            v0.x = fmaxf(fmaf(bna.x, v0.x, bnb.x), 0.f);
            v0.y = fmaxf(fmaf(bna.y, v0.y, bnb.y), 0.f);
            v0.z = fmaxf(fmaf(bna.z, v0.z, bnb.z), 0.f);
            v0.w = fmaxf(fmaf(bna.w, v0.w, bnb.w), 0.f);
        }
        acc.x += v0.x; acc.y += v0.y; acc.z += v0.z; acc.w += v0.w;
    }

    red[rl][grp][cg] = acc;
    __syncthreads();

    int col = t6;
    const float* r0 = reinterpret_cast<const float*>(&red[rl][0][col >> 2]);
    const float* r1 = reinterpret_cast<const float*>(&red[rl][1][col >> 2]);
    const float* r2 = reinterpret_cast<const float*>(&red[rl][2][col >> 2]);
    const float* r3 = reinterpret_cast<const float*>(&red[rl][3][col >> 2]);
    int comp = col & 3;
    float s = (r0[comp] + r1[comp]) + (r2[comp] + r3[comp]);
    out[(size_t)r * HDIM + col] = s / (float)g_nnz[r];
}

// ---------------- K3: fused GEMM [16384,64]@[64,64] + bias + BN-stat partials
// MODE==1 applies relu(a*x+b) (previous inner BN) to the input tile.
template <int MODE>
__global__ __launch_bounds__(256) void gemm64(const float* __restrict__ in,
                                              const float* __restrict__ W,
                                              const float* __restrict__ bias,
                                              float* __restrict__ out,
                                              float* __restrict__ part) {
    __shared__ float Ws[64 * 64];
    __shared__ float Is[16][68];            // padded vs bank conflicts

    int tid = threadIdx.x;
    for (int i = tid; i < 4096; i += 256) Ws[i] = W[i];

    int row0 = blockIdx.x * 16;
    for (int i = tid; i < 1024; i += 256) {
        int rr = i >> 6, cc = i & 63;
        float v = in[(size_t)(row0 + rr) * HDIM + cc];
        if (MODE == 1)
            v = fmaxf(fmaf(g_ab[cc], v, g_ab[64 + cc]), 0.f);
        Is[rr][cc] = v;
    }
    __syncthreads();

    int ty = tid >> 4;          // output row within tile
    int tx = tid & 15;          // 4-col group
    float acc[4];
    #pragma unroll
    for (int j = 0; j < 4; j++) acc[j] = bias[tx * 4 + j];

    #pragma unroll
    for (int k = 0; k < 64; k++) {
        float iv = Is[ty][k];
        #pragma unroll
        for (int j = 0; j < 4; j++)
            acc[j] = fmaf(iv, Ws[k * 64 + tx * 4 + j], acc[j]);
    }

    size_t obase = (size_t)(row0 + ty) * HDIM + tx * 4;
    #pragma unroll
    for (int j = 0; j < 4; j++) out[obase + j] = acc[j];

    // per-block column stats (sum, sumsq) -> g_part (deterministic, no atomics)
    __syncthreads();
    #pragma unroll
    for (int j = 0; j < 4; j++) Is[ty][tx * 4 + j] = acc[j];
    __syncthreads();
    if (tid < 64) {
        float s = 0.f;
        #pragma unroll
        for (int r = 0; r < 16; r++) s += Is[r][tid];
        part[(size_t)blockIdx.x * 128 + tid] = s;
    }
    __syncthreads();
    #pragma unroll
    for (int j = 0; j < 4; j++) Is[ty][tx * 4 + j] = acc[j] * acc[j];
    __syncthreads();
    if (tid < 64) {
        float s = 0.f;
        #pragma unroll
        for (int r = 0; r < 16; r++) s += Is[r][tid];
        part[(size_t)blockIdx.x * 128 + 64 + tid] = s;
    }
}

// ---------------- K4: reduce partials -> BN affine coefficients ----------------
__global__ __launch_bounds__(256) void bn_finalize(const float* __restrict__ g,
                                                   const float* __restrict__ be) {
    int c = blockIdx.x;                      // column 0..63
    int t = threadIdx.x;

    float s = 0.f, q = 0.f;
    #pragma unroll 4
    for (int b = t; b < NBLK; b += 256) {
        s += g_part[(size_t)b * 128 + c];
        q += g_part[(size_t)b * 128 + 64 + c];
    }
    __shared__ float ss[256];
    __shared__ float qq[256];
    ss[t] = s; qq[t] = q;
    __syncthreads();
    #pragma unroll
    for (int o = 128; o > 0; o >>= 1) {
        if (t < o) { ss[t] += ss[t + o]; qq[t] += qq[t + o]; }
        __syncthreads();
    }
    if (t == 0) {
        const float invn = 1.0f / (float)N_NODES;
        float mean = ss[0] * invn;
        float var  = qq[0] * invn - mean * mean;
        float a = g[c] * rsqrtf(var + BN_EPS);
        g_ab[c]      = a;
        g_ab[64 + c] = be[c] - mean * a;
    }
}

// ---------------- K5: elementwise h = relu(a*t2 + b) (final layer only) ----------------
__global__ __launch_bounds__(256) void apply_bn_relu(const float* __restrict__ t2,
                                                     float* __restrict__ h) {
    int i = blockIdx.x * 256 + threadIdx.x;
    int c = i & 63;
    h[i] = fmaxf(fmaf(g_ab[c], t2[i], g_ab[64 + c]), 0.f);
}

// ---------------- K6: pooled_h = graph_pool @ h  (general dense, zero-skip) ----------------
__global__ __launch_bounds__(256) void pool(const float* __restrict__ gp,
                                            const float* __restrict__ h,
                                            float* __restrict__ out) {
    int g = blockIdx.x;                 // 128 graphs
    int c    = threadIdx.x & 63;
    int lane = threadIdx.x >> 6;        // 4 node-lanes (warp-uniform)
    const float* gprow = gp + (size_t)g * N_NODES;

    float acc = 0.f;
    for (int n0 = lane; n0 < N_NODES; n0 += 32) {
        #pragma unroll
        for (int u = 0; u < 8; u++) {
            int n = n0 + u * 4;
            float w = __ldcs(gprow + n);
            if (w != 0.f) acc = fmaf(w, h[(size_t)n * HDIM + c], acc);
        }
    }
    __shared__ float red[4][64];
    red[lane][c] = acc;
    __syncthreads();
    if (threadIdx.x < 64)
        out[(size_t)g * HDIM + threadIdx.x] =
            (red[0][threadIdx.x] + red[1][threadIdx.x]) +
            (red[2][threadIdx.x] + red[3][threadIdx.x]);
}

// ---------------- launch ----------------
extern "C" void kernel_launch(void* const* d_in, const int* in_sizes, int n_in,
                              void* d_out, int out_size) {
    const float* x   = (const float*)d_in[0];
    const float* adj = (const float*)d_in[1];
    const float* gp  = (const float*)d_in[2];

    const float* P[16];
    for (int i = 0; i < 16; i++) P[i] = (const float*)d_in[3 + i];

    float* out      = (float*)d_out;
    float* h_nodes  = out + 128 * HDIM;   // [16384,64] after the [128,64] readout

    float *pooled, *t, *t2, *part;
    cudaGetSymbolAddress((void**)&pooled, g_pooled);
    cudaGetSymbolAddress((void**)&t,      g_t);
    cudaGetSymbolAddress((void**)&t2,     g_t2);
    cudaGetSymbolAddress((void**)&part,   g_part);

    // 1) fused: adj scan -> CSR + degrees + layer-0 mean aggregation
    scan_agg<<<2048, 256>>>(adj, x, pooled);

    // ---- layer 0 MLP ----
    gemm64<0><<<NBLK, 256>>>(pooled, P[0], P[1], t, part);
    bn_finalize<<<64, 256>>>(P[2], P[3]);               // g1_0, be1_0
    gemm64<1><<<NBLK, 256>>>(t, P[4], P[5], t2, part);
    bn_finalize<<<64, 256>>>(P[6], P[7]);               // g_0, be_0

    // ---- layer 1 (outer BN+ReLU of layer 0 fused into the gather) ----
    agg<1><<<N_NODES / 4, 256>>>(t2, pooled);           // launch #6 -> ncu window
    gemm64<0><<<NBLK, 256>>>(pooled, P[8], P[9], t, part);
    bn_finalize<<<64, 256>>>(P[10], P[11]);             // g1_1, be1_1
    gemm64<1><<<NBLK, 256>>>(t, P[12], P[13], t2, part);
    bn_finalize<<<64, 256>>>(P[14], P[15]);             // g_1, be_1
    apply_bn_relu<<<(N_NODES * HDIM) / 256, 256>>>(t2, h_nodes);

    // ---- graph readout ----
    pool<<<128, 256>>>(gp, h_nodes, out);

    (void)in_sizes; (void)n_in; (void)out_size;
}

// round 8
// speedup vs baseline: 1.3684x; 1.0572x over previous
#include <cuda_runtime.h>
#include <cstdint>

#define N_NODES 16384
#define HDIM    64
#define MAXN    160          // max nnz/row: Binomial(16384,0.004)+1, mean 66, ~11 sigma headroom
#define NBLK    256          // gemm blocks (64 rows each)
#define BN_EPS  1e-5f

// ---------------- device scratch (no allocations allowed) ----------------
__device__ int   g_idx[N_NODES * MAXN];     // CSR-ish column indices per row
__device__ int   g_nnz[N_NODES];            // row degree (= row sum of adj)
__device__ __align__(16) float g_pooled[N_NODES * HDIM];
__device__ __align__(16) float g_t[N_NODES * HDIM];
__device__ __align__(16) float g_t2[N_NODES * HDIM];
__device__ __align__(16) float g_part[NBLK * 128];   // per-block [sum(64) | sumsq(64)]
__device__ __align__(16) float g_ab[128];            // BN affine: a[64], b[64]

// ---------------- K1: fused adj scan + layer-0 mean aggregation ----------------
// One warp per row. Phase 1 streams the 64KB row with 4 back-to-back LDG.128
// per thread per iteration (loads issued before any data-dependent test ->
// MLP>=4), compacting nonzero column ids into SMEM (+ mirror to g_idx).
// Phase 2 gathers x[j,:] over the id list -> pooled[r,:] = mean.
__global__ __launch_bounds__(256) void scan_agg(const float* __restrict__ adj,
                                                const float* __restrict__ x,
                                                float* __restrict__ pooled) {
    int lane   = threadIdx.x & 31;
    int wlocal = threadIdx.x >> 5;
    int row    = (blockIdx.x << 3) + wlocal;        // 2048 blocks * 8 warps

    __shared__ int snnz[8];
    __shared__ int ids[8][MAXN];
    if (lane == 0) snnz[wlocal] = 0;
    __syncwarp();

    const uint4* base = reinterpret_cast<const uint4*>(adj + (size_t)row * N_NODES);
    int* rowidx = g_idx + (size_t)row * MAXN;

    // ---- phase 1: stream + compact (batched loads) ----
    #pragma unroll 2
    for (int t = 0; t < 32; t++) {
        int f4 = t * 128 + lane * 4;            // thread covers 64B contiguous
        uint4 u0 = __ldcs(base + f4);           // 4 LDG.128 issued back-to-back
        uint4 u1 = __ldcs(base + f4 + 1);
        uint4 u2 = __ldcs(base + f4 + 2);
        uint4 u3 = __ldcs(base + f4 + 3);
        unsigned m0 = u0.x | u0.y | u0.z | u0.w;
        unsigned m1 = u1.x | u1.y | u1.z | u1.w;
        unsigned m2 = u2.x | u2.y | u2.z | u2.w;
        unsigned m3 = u3.x | u3.y | u3.z | u3.w;
        if (m0 | m1 | m2 | m3) {
            unsigned w[16] = {u0.x, u0.y, u0.z, u0.w, u1.x, u1.y, u1.z, u1.w,
                              u2.x, u2.y, u2.z, u2.w, u3.x, u3.y, u3.z, u3.w};
            int col0 = f4 * 4;
            int loc[16];
            int cnt = 0;
            #pragma unroll
            for (int k = 0; k < 16; k++)
                if (w[k]) loc[cnt++] = col0 + k;
            int pos = atomicAdd(&snnz[wlocal], cnt);
            if (pos + cnt <= MAXN) {
                for (int i = 0; i < cnt; i++) {
                    ids[wlocal][pos + i] = loc[i];
                    rowidx[pos + i]      = loc[i];
                }
            }
        }
    }
    __syncwarp();
    int nnz = snnz[wlocal];
    if (lane == 0) g_nnz[row] = nnz;

    // ---- phase 2: gather x over the id list -> pooled[row,:] ----
    int half = lane >> 4;                   // 0/1: alternating list positions
    int cg   = lane & 15;                   // column group (4 floats)
    float4 acc = make_float4(0.f, 0.f, 0.f, 0.f);

    int k = half;
    for (; k + 2 < nnz; k += 4) {
        int i0 = ids[wlocal][k];
        int i1 = ids[wlocal][k + 2];
        float4 v0 = *reinterpret_cast<const float4*>(x + (size_t)i0 * HDIM + cg * 4);
        float4 v1 = *reinterpret_cast<const float4*>(x + (size_t)i1 * HDIM + cg * 4);
        acc.x += v0.x + v1.x; acc.y += v0.y + v1.y;
        acc.z += v0.z + v1.z; acc.w += v0.w + v1.w;
    }
    if (k < nnz) {
        int i0 = ids[wlocal][k];
        float4 v0 = *reinterpret_cast<const float4*>(x + (size_t)i0 * HDIM + cg * 4);
        acc.x += v0.x; acc.y += v0.y; acc.z += v0.z; acc.w += v0.w;
    }
    acc.x += __shfl_down_sync(0xffffffffu, acc.x, 16);
    acc.y += __shfl_down_sync(0xffffffffu, acc.y, 16);
    acc.z += __shfl_down_sync(0xffffffffu, acc.z, 16);
    acc.w += __shfl_down_sync(0xffffffffu, acc.w, 16);
    if (half == 0) {
        float inv = 1.0f / (float)nnz;
        float4 r = make_float4(acc.x * inv, acc.y * inv, acc.z * inv, acc.w * inv);
        *reinterpret_cast<float4*>(pooled + (size_t)row * HDIM + cg * 4) = r;
    }
}

// ---------------- K2: sparse mean aggregation, float4 gather, MLP=4 ----------------
template <int APPLY>
__global__ __launch_bounds__(256) void agg(const float* __restrict__ src,
                                           float* __restrict__ out) {
    int rl  = threadIdx.x >> 6;             // 0..3 row within block
    int t6  = threadIdx.x & 63;
    int grp = t6 >> 4;                      // 0..3 neighbor group
    int cg  = t6 & 15;                      // column group (4 floats)
    int r   = ((int)blockIdx.x << 2) + rl;

    __shared__ int    ids[4][MAXN];
    __shared__ float4 red[4][4][16];        // [rl][grp][cg]

    int nnz = g_nnz[r];
    for (int i = t6; i < nnz; i += 64) ids[rl][i] = g_idx[(size_t)r * MAXN + i];
    __syncthreads();

    float4 bna, bnb;
    if (APPLY) {
        bna = *reinterpret_cast<const float4*>(&g_ab[cg * 4]);
        bnb = *reinterpret_cast<const float4*>(&g_ab[64 + cg * 4]);
    }

    float4 acc = make_float4(0.f, 0.f, 0.f, 0.f);
    int k = grp;
    for (; k + 12 < nnz; k += 16) {         // 4 loads in flight per thread
        int i0 = ids[rl][k];
        int i1 = ids[rl][k + 4];
        int i2 = ids[rl][k + 8];
        int i3 = ids[rl][k + 12];
        float4 v0 = *reinterpret_cast<const float4*>(src + (size_t)i0 * HDIM + cg * 4);
        float4 v1 = *reinterpret_cast<const float4*>(src + (size_t)i1 * HDIM + cg * 4);
        float4 v2 = *reinterpret_cast<const float4*>(src + (size_t)i2 * HDIM + cg * 4);
        float4 v3 = *reinterpret_cast<const float4*>(src + (size_t)i3 * HDIM + cg * 4);
        if (APPLY) {
            v0.x = fmaxf(fmaf(bna.x, v0.x, bnb.x), 0.f);
            v0.y = fmaxf(fmaf(bna.y, v0.y, bnb.y), 0.f);
            v0.z = fmaxf(fmaf(bna.z, v0.z, bnb.z), 0.f);
            v0.w = fmaxf(fmaf(bna.w, v0.w, bnb.w), 0.f);
            v1.x = fmaxf(fmaf(bna.x, v1.x, bnb.x), 0.f);
            v1.y = fmaxf(fmaf(bna.y, v1.y, bnb.y), 0.f);
            v1.z = fmaxf(fmaf(bna.z, v1.z, bnb.z), 0.f);
            v1.w = fmaxf(fmaf(bna.w, v1.w, bnb.w), 0.f);
            v2.x = fmaxf(fmaf(bna.x, v2.x, bnb.x), 0.f);
            v2.y = fmaxf(fmaf(bna.y, v2.y, bnb.y), 0.f);
            v2.z = fmaxf(fmaf(bna.z, v2.z, bnb.z), 0.f);
            v2.w = fmaxf(fmaf(bna.w, v2.w, bnb.w), 0.f);
            v3.x = fmaxf(fmaf(bna.x, v3.x, bnb.x), 0.f);
            v3.y = fmaxf(fmaf(bna.y, v3.y, bnb.y), 0.f);
            v3.z = fmaxf(fmaf(bna.z, v3.z, bnb.z), 0.f);
            v3.w = fmaxf(fmaf(bna.w, v3.w, bnb.w), 0.f);
        }
        acc.x += (v0.x + v1.x) + (v2.x + v3.x);
        acc.y += (v0.y + v1.y) + (v2.y + v3.y);
        acc.z += (v0.z + v1.z) + (v2.z + v3.z);
        acc.w += (v0.w + v1.w) + (v2.w + v3.w);
    }
    for (; k < nnz; k += 4) {
        int i0 = ids[rl][k];
        float4 v0 = *reinterpret_cast<const float4*>(src + (size_t)i0 * HDIM + cg * 4);
        if (APPLY) {
            v0.x = fmaxf(fmaf(bna.x, v0.x, bnb.x), 0.f);
            v0.y = fmaxf(fmaf(bna.y, v0.y, bnb.y), 0.f);
            v0.z = fmaxf(fmaf(bna.z, v0.z, bnb.z), 0.f);
            v0.w = fmaxf(fmaf(bna.w, v0.w, bnb.w), 0.f);
        }
        acc.x += v0.x; acc.y += v0.y; acc.z += v0.z; acc.w += v0.w;
    }

    red[rl][grp][cg] = acc;
    __syncthreads();

    int col = t6;
    const float* r0 = reinterpret_cast<const float*>(&red[rl][0][col >> 2]);
    const float* r1 = reinterpret_cast<const float*>(&red[rl][1][col >> 2]);
    const float* r2 = reinterpret_cast<const float*>(&red[rl][2][col >> 2]);
    const float* r3 = reinterpret_cast<const float*>(&red[rl][3][col >> 2]);
    int comp = col & 3;
    float s = (r0[comp] + r1[comp]) + (r2[comp] + r3[comp]);
    out[(size_t)r * HDIM + col] = s / (float)g_nnz[r];
}

// ---------------- K3: register-blocked GEMM [16384,64]@[64,64] + bias + BN stats
// 64-row tiles, each thread computes a 4x4 output block; k unrolled by 4 with
// float4 LDS on both operands (8 LDS.128 per 64 FFMA).
// MODE==1 applies relu(a*x+b) (previous inner BN) to the input tile.
template <int MODE>
__global__ __launch_bounds__(256) void gemm64(const float* __restrict__ in,
                                              const float* __restrict__ W,
                                              const float* __restrict__ bias,
                                              float* __restrict__ out,
                                              float* __restrict__ part) {
    __shared__ __align__(16) float Ws[64 * 64];      // [k][n]
    __shared__ __align__(16) float Is[64][72];       // 72: 16B-aligned row pad
    __shared__ float redm[16][64];

    int tid = threadIdx.x;
    const float4* W4 = reinterpret_cast<const float4*>(W);
    float4* Ws4 = reinterpret_cast<float4*>(Ws);
    #pragma unroll
    for (int i = tid; i < 1024; i += 256) Ws4[i] = W4[i];

    int row0 = (int)blockIdx.x * 64;
    const float4* in4 = reinterpret_cast<const float4*>(in + (size_t)row0 * HDIM);
    #pragma unroll
    for (int i = tid; i < 1024; i += 256) {
        int rr = i >> 4, cg = i & 15;
        float4 v = in4[i];
        if (MODE == 1) {
            float4 a4 = *reinterpret_cast<const float4*>(&g_ab[cg * 4]);
            float4 b4 = *reinterpret_cast<const float4*>(&g_ab[64 + cg * 4]);
            v.x = fmaxf(fmaf(a4.x, v.x, b4.x), 0.f);
            v.y = fmaxf(fmaf(a4.y, v.y, b4.y), 0.f);
            v.z = fmaxf(fmaf(a4.z, v.z, b4.z), 0.f);
            v.w = fmaxf(fmaf(a4.w, v.w, b4.w), 0.f);
        }
        *reinterpret_cast<float4*>(&Is[rr][cg * 4]) = v;
    }
    __syncthreads();

    int ty = tid >> 4;              // row group: rows ty*4..ty*4+3
    int tx = tid & 15;              // col group: cols tx*4..tx*4+3

    float acc[4][4];
    float4 bv = *reinterpret_cast<const float4*>(bias + tx * 4);
    #pragma unroll
    for (int r = 0; r < 4; r++) {
        acc[r][0] = bv.x; acc[r][1] = bv.y; acc[r][2] = bv.z; acc[r][3] = bv.w;
    }

    #pragma unroll
    for (int k = 0; k < 64; k += 4) {
        float4 w0 = *reinterpret_cast<const float4*>(&Ws[(k + 0) * 64 + tx * 4]);
        float4 w1 = *reinterpret_cast<const float4*>(&Ws[(k + 1) * 64 + tx * 4]);
        float4 w2 = *reinterpret_cast<const float4*>(&Ws[(k + 2) * 64 + tx * 4]);
        float4 w3 = *reinterpret_cast<const float4*>(&Ws[(k + 3) * 64 + tx * 4]);
        #pragma unroll
        for (int r = 0; r < 4; r++) {
            float4 iv = *reinterpret_cast<const float4*>(&Is[ty * 4 + r][k]);
            acc[r][0] = fmaf(iv.x, w0.x, acc[r][0]);
            acc[r][1] = fmaf(iv.x, w0.y, acc[r][1]);
            acc[r][2] = fmaf(iv.x, w0.z, acc[r][2]);
            acc[r][3] = fmaf(iv.x, w0.w, acc[r][3]);
            acc[r][0] = fmaf(iv.y, w1.x, acc[r][0]);
            acc[r][1] = fmaf(iv.y, w1.y, acc[r][1]);
            acc[r][2] = fmaf(iv.y, w1.z, acc[r][2]);
            acc[r][3] = fmaf(iv.y, w1.w, acc[r][3]);
            acc[r][0] = fmaf(iv.z, w2.x, acc[r][0]);
            acc[r][1] = fmaf(iv.z, w2.y, acc[r][1]);
            acc[r][2] = fmaf(iv.z, w2.z, acc[r][2]);
            acc[r][3] = fmaf(iv.z, w2.w, acc[r][3]);
            acc[r][0] = fmaf(iv.w, w3.x, acc[r][0]);
            acc[r][1] = fmaf(iv.w, w3.y, acc[r][1]);
            acc[r][2] = fmaf(iv.w, w3.z, acc[r][2]);
            acc[r][3] = fmaf(iv.w, w3.w, acc[r][3]);
        }
    }

    // store outputs (float4 per row)
    #pragma unroll
    for (int r = 0; r < 4; r++) {
        float4 o = make_float4(acc[r][0], acc[r][1], acc[r][2], acc[r][3]);
        *reinterpret_cast<float4*>(out + (size_t)(row0 + ty * 4 + r) * HDIM + tx * 4) = o;
    }

    // per-block column stats: sum then sumsq (two passes through redm)
    float s[4];
    #pragma unroll
    for (int j = 0; j < 4; j++)
        s[j] = (acc[0][j] + acc[1][j]) + (acc[2][j] + acc[3][j]);
    #pragma unroll
    for (int j = 0; j < 4; j++) redm[ty][tx * 4 + j] = s[j];
    __syncthreads();
    if (tid < 64) {
        float v = 0.f;
        #pragma unroll
        for (int i = 0; i < 16; i++) v += redm[i][tid];
        part[(size_t)blockIdx.x * 128 + tid] = v;
    }
    __syncthreads();
    #pragma unroll
    for (int j = 0; j < 4; j++) {
        float q = (acc[0][j] * acc[0][j] + acc[1][j] * acc[1][j]) +
                  (acc[2][j] * acc[2][j] + acc[3][j] * acc[3][j]);
        redm[ty][tx * 4 + j] = q;
    }
    __syncthreads();
    if (tid < 64) {
        float v = 0.f;
        #pragma unroll
        for (int i = 0; i < 16; i++) v += redm[i][tid];
        part[(size_t)blockIdx.x * 128 + 64 + tid] = v;
    }
}

// ---------------- K4: reduce partials -> BN affine coefficients ----------------
__global__ __launch_bounds__(256) void bn_finalize(const float* __restrict__ g,
                                                   const float* __restrict__ be) {
    int c = blockIdx.x;                      // column 0..63
    int t = threadIdx.x;

    float s = 0.f, q = 0.f;
    for (int b = t; b < NBLK; b += 256) {
        s += g_part[(size_t)b * 128 + c];
        q += g_part[(size_t)b * 128 + 64 + c];
    }
    __shared__ float ss[256];
    __shared__ float qq[256];
    ss[t] = s; qq[t] = q;
    __syncthreads();
    #pragma unroll
    for (int o = 128; o > 0; o >>= 1) {
        if (t < o) { ss[t] += ss[t + o]; qq[t] += qq[t + o]; }
        __syncthreads();
    }
    if (t == 0) {
        const float invn = 1.0f / (float)N_NODES;
        float mean = ss[0] * invn;
        float var  = qq[0] * invn - mean * mean;
        float a = g[c] * rsqrtf(var + BN_EPS);
        g_ab[c]      = a;
        g_ab[64 + c] = be[c] - mean * a;
    }
}

// ---------------- K5: elementwise h = relu(a*t2 + b) (final layer only) ----------------
__global__ __launch_bounds__(256) void apply_bn_relu(const float* __restrict__ t2,
                                                     float* __restrict__ h) {
    int i = blockIdx.x * 256 + threadIdx.x;
    int c = i & 63;
    h[i] = fmaxf(fmaf(g_ab[c], t2[i], g_ab[64 + c]), 0.f);
}

// ---------------- K6: pooled_h = graph_pool @ h  (general dense, zero-skip) ----------------
__global__ __launch_bounds__(256) void pool(const float* __restrict__ gp,
                                            const float* __restrict__ h,
                                            float* __restrict__ out) {
    int g = blockIdx.x;                 // 128 graphs
    int c    = threadIdx.x & 63;
    int lane = threadIdx.x >> 6;        // 4 node-lanes (warp-uniform)
    const float* gprow = gp + (size_t)g * N_NODES;

    float acc = 0.f;
    for (int n0 = lane; n0 < N_NODES; n0 += 32) {
        #pragma unroll
        for (int u = 0; u < 8; u++) {
            int n = n0 + u * 4;
            float w = __ldcs(gprow + n);
            if (w != 0.f) acc = fmaf(w, h[(size_t)n * HDIM + c], acc);
        }
    }
    __shared__ float red[4][64];
    red[lane][c] = acc;
    __syncthreads();
    if (threadIdx.x < 64)
        out[(size_t)g * HDIM + threadIdx.x] =
            (red[0][threadIdx.x] + red[1][threadIdx.x]) +
            (red[2][threadIdx.x] + red[3][threadIdx.x]);
}

// ---------------- launch ----------------
extern "C" void kernel_launch(void* const* d_in, const int* in_sizes, int n_in,
                              void* d_out, int out_size) {
    const float* x   = (const float*)d_in[0];
    const float* adj = (const float*)d_in[1];
    const float* gp  = (const float*)d_in[2];

    const float* P[16];
    for (int i = 0; i < 16; i++) P[i] = (const float*)d_in[3 + i];

    float* out      = (float*)d_out;
    float* h_nodes  = out + 128 * HDIM;   // [16384,64] after the [128,64] readout

    float *pooled, *t, *t2, *part;
    cudaGetSymbolAddress((void**)&pooled, g_pooled);
    cudaGetSymbolAddress((void**)&t,      g_t);
    cudaGetSymbolAddress((void**)&t2,     g_t2);
    cudaGetSymbolAddress((void**)&part,   g_part);

    // 1) fused: adj scan -> CSR + degrees + layer-0 mean aggregation
    scan_agg<<<2048, 256>>>(adj, x, pooled);

    // ---- layer 0 MLP ----
    gemm64<0><<<NBLK, 256>>>(pooled, P[0], P[1], t, part);
    bn_finalize<<<64, 256>>>(P[2], P[3]);               // g1_0, be1_0
    gemm64<1><<<NBLK, 256>>>(t, P[4], P[5], t2, part);
    bn_finalize<<<64, 256>>>(P[6], P[7]);               // g_0, be_0

    // ---- layer 1 (outer BN+ReLU of layer 0 fused into the gather) ----
    agg<1><<<N_NODES / 4, 256>>>(t2, pooled);           // launch #6 -> ncu window
    gemm64<0><<<NBLK, 256>>>(pooled, P[8], P[9], t, part);
    bn_finalize<<<64, 256>>>(P[10], P[11]);             // g1_1, be1_1
    gemm64<1><<<NBLK, 256>>>(t, P[12], P[13], t2, part);
    bn_finalize<<<64, 256>>>(P[14], P[15]);             // g_1, be_1
    apply_bn_relu<<<(N_NODES * HDIM) / 256, 256>>>(t2, h_nodes);

    // ---- graph readout ----
    pool<<<128, 256>>>(gp, h_nodes, out);

    (void)in_sizes; (void)n_in; (void)out_size;
}

// round 9
// speedup vs baseline: 1.3796x; 1.0082x over previous
#include <cuda_runtime.h>
#include <cstdint>

#define N_NODES 16384
#define HDIM    64
#define MAXN    160          // max nnz/row: Binomial(16384,0.004)+1, mean 66, ~11 sigma headroom
#define NBLK    512          // gemm blocks (32 rows each)
#define BN_EPS  1e-5f

// ---------------- device scratch (no allocations allowed) ----------------
__device__ int   g_idx[N_NODES * MAXN];     // CSR-ish column indices per row
__device__ int   g_nnz[N_NODES];            // row degree (= row sum of adj)
__device__ __align__(16) float g_pooled[N_NODES * HDIM];
__device__ __align__(16) float g_t[N_NODES * HDIM];
__device__ __align__(16) float g_t2[N_NODES * HDIM];
__device__ __align__(16) float g_part[NBLK * 128];   // per-block [sum(64) | sumsq(64)]
__device__ __align__(16) float g_ab[128];            // BN affine: a[64], b[64]

// ---------------- K1: fused adj scan + layer-0 mean aggregation ----------------
// One warp per row. Phase 1 streams the 64KB row with 8 FULLY-COALESCED
// LDG.128 per thread per iteration (each warp load = 512B contiguous = 4 L1
// lines = 4 wavefronts, the 128B/wf optimum; loads issue before any
// data-dependent test -> MLP=8). Nonzero column ids are compacted into SMEM
// (+ mirrored to g_idx for layer 1). Phase 2 gathers x[j,:] over the id list
// -> pooled[r,:] = mean; gather overlaps other warps' DRAM streaming.
__global__ __launch_bounds__(256) void scan_agg(const float* __restrict__ adj,
                                                const float* __restrict__ x,
                                                float* __restrict__ pooled) {
    int lane   = threadIdx.x & 31;
    int wlocal = threadIdx.x >> 5;
    int row    = (blockIdx.x << 3) + wlocal;        // 2048 blocks * 8 warps

    __shared__ int snnz[8];
    __shared__ int ids[8][MAXN];
    if (lane == 0) snnz[wlocal] = 0;
    __syncwarp();

    const uint4* base = reinterpret_cast<const uint4*>(adj + (size_t)row * N_NODES);
    int* rowidx = g_idx + (size_t)row * MAXN;

    // ---- phase 1: stream + compact (coalesced batched loads) ----
    // iter covers 4KB: 8 warp-loads of 512B each; thread's k-th word is at
    // uint4 index ibase + k*32 + lane.
    for (int t = 0; t < 16; t++) {
        int ibase = t * 256;
        uint4 u[8];
        #pragma unroll
        for (int k = 0; k < 8; k++)
            u[k] = __ldcs(base + ibase + k * 32 + lane);

        unsigned any = 0;
        #pragma unroll
        for (int k = 0; k < 8; k++)
            any |= (u[k].x | u[k].y | u[k].z | u[k].w);

        if (any) {
            int loc[32];
            int cnt = 0;
            #pragma unroll
            for (int k = 0; k < 8; k++) {
                unsigned mk = u[k].x | u[k].y | u[k].z | u[k].w;
                if (mk) {
                    int col0 = (ibase + k * 32 + lane) * 4;
                    if (u[k].x) loc[cnt++] = col0;
                    if (u[k].y) loc[cnt++] = col0 + 1;
                    if (u[k].z) loc[cnt++] = col0 + 2;
                    if (u[k].w) loc[cnt++] = col0 + 3;
                }
            }
            int pos = atomicAdd(&snnz[wlocal], cnt);
            if (pos + cnt <= MAXN) {
                for (int i = 0; i < cnt; i++) {
                    ids[wlocal][pos + i] = loc[i];
                    rowidx[pos + i]      = loc[i];
                }
            }
        }
    }
    __syncwarp();
    int nnz = snnz[wlocal];
    if (lane == 0) g_nnz[row] = nnz;

    // ---- phase 2: gather x over the id list -> pooled[row,:] ----
    int half = lane >> 4;                   // 0/1: alternating list positions
    int cg   = lane & 15;                   // column group (4 floats)
    float4 acc = make_float4(0.f, 0.f, 0.f, 0.f);

    int k = half;
    for (; k + 2 < nnz; k += 4) {
        int i0 = ids[wlocal][k];
        int i1 = ids[wlocal][k + 2];
        float4 v0 = *reinterpret_cast<const float4*>(x + (size_t)i0 * HDIM + cg * 4);
        float4 v1 = *reinterpret_cast<const float4*>(x + (size_t)i1 * HDIM + cg * 4);
        acc.x += v0.x + v1.x; acc.y += v0.y + v1.y;
        acc.z += v0.z + v1.z; acc.w += v0.w + v1.w;
    }
    if (k < nnz) {
        int i0 = ids[wlocal][k];
        float4 v0 = *reinterpret_cast<const float4*>(x + (size_t)i0 * HDIM + cg * 4);
        acc.x += v0.x; acc.y += v0.y; acc.z += v0.z; acc.w += v0.w;
    }
    acc.x += __shfl_down_sync(0xffffffffu, acc.x, 16);
    acc.y += __shfl_down_sync(0xffffffffu, acc.y, 16);
    acc.z += __shfl_down_sync(0xffffffffu, acc.z, 16);
    acc.w += __shfl_down_sync(0xffffffffu, acc.w, 16);
    if (half == 0) {
        float inv = 1.0f / (float)nnz;
        float4 r = make_float4(acc.x * inv, acc.y * inv, acc.z * inv, acc.w * inv);
        *reinterpret_cast<float4*>(pooled + (size_t)row * HDIM + cg * 4) = r;
    }
}

// ---------------- K2: sparse mean aggregation, float4 gather, MLP=4 ----------------
template <int APPLY>
__global__ __launch_bounds__(256) void agg(const float* __restrict__ src,
                                           float* __restrict__ out) {
    int rl  = threadIdx.x >> 6;             // 0..3 row within block
    int t6  = threadIdx.x & 63;
    int grp = t6 >> 4;                      // 0..3 neighbor group
    int cg  = t6 & 15;                      // column group (4 floats)
    int r   = ((int)blockIdx.x << 2) + rl;

    __shared__ int    ids[4][MAXN];
    __shared__ float4 red[4][4][16];        // [rl][grp][cg]

    int nnz = g_nnz[r];
    for (int i = t6; i < nnz; i += 64) ids[rl][i] = g_idx[(size_t)r * MAXN + i];
    __syncthreads();

    float4 bna, bnb;
    if (APPLY) {
        bna = *reinterpret_cast<const float4*>(&g_ab[cg * 4]);
        bnb = *reinterpret_cast<const float4*>(&g_ab[64 + cg * 4]);
    }

    float4 acc = make_float4(0.f, 0.f, 0.f, 0.f);
    int k = grp;
    for (; k + 12 < nnz; k += 16) {         // 4 loads in flight per thread
        int i0 = ids[rl][k];
        int i1 = ids[rl][k + 4];
        int i2 = ids[rl][k + 8];
        int i3 = ids[rl][k + 12];
        float4 v0 = *reinterpret_cast<const float4*>(src + (size_t)i0 * HDIM + cg * 4);
        float4 v1 = *reinterpret_cast<const float4*>(src + (size_t)i1 * HDIM + cg * 4);
        float4 v2 = *reinterpret_cast<const float4*>(src + (size_t)i2 * HDIM + cg * 4);
        float4 v3 = *reinterpret_cast<const float4*>(src + (size_t)i3 * HDIM + cg * 4);
        if (APPLY) {
            v0.x = fmaxf(fmaf(bna.x, v0.x, bnb.x), 0.f);
            v0.y = fmaxf(fmaf(bna.y, v0.y, bnb.y), 0.f);
            v0.z = fmaxf(fmaf(bna.z, v0.z, bnb.z), 0.f);
            v0.w = fmaxf(fmaf(bna.w, v0.w, bnb.w), 0.f);
            v1.x = fmaxf(fmaf(bna.x, v1.x, bnb.x), 0.f);
            v1.y = fmaxf(fmaf(bna.y, v1.y, bnb.y), 0.f);
            v1.z = fmaxf(fmaf(bna.z, v1.z, bnb.z), 0.f);
            v1.w = fmaxf(fmaf(bna.w, v1.w, bnb.w), 0.f);
            v2.x = fmaxf(fmaf(bna.x, v2.x, bnb.x), 0.f);
            v2.y = fmaxf(fmaf(bna.y, v2.y, bnb.y), 0.f);
            v2.z = fmaxf(fmaf(bna.z, v2.z, bnb.z), 0.f);
            v2.w = fmaxf(fmaf(bna.w, v2.w, bnb.w), 0.f);
            v3.x = fmaxf(fmaf(bna.x, v3.x, bnb.x), 0.f);
            v3.y = fmaxf(fmaf(bna.y, v3.y, bnb.y), 0.f);
            v3.z = fmaxf(fmaf(bna.z, v3.z, bnb.z), 0.f);
            v3.w = fmaxf(fmaf(bna.w, v3.w, bnb.w), 0.f);
        }
        acc.x += (v0.x + v1.x) + (v2.x + v3.x);
        acc.y += (v0.y + v1.y) + (v2.y + v3.y);
        acc.z += (v0.z + v1.z) + (v2.z + v3.z);
        acc.w += (v0.w + v1.w) + (v2.w + v3.w);
    }
    for (; k < nnz; k += 4) {
        int i0 = ids[rl][k];
        float4 v0 = *reinterpret_cast<const float4*>(src + (size_t)i0 * HDIM + cg * 4);
        if (APPLY) {
            v0.x = fmaxf(fmaf(bna.x, v0.x, bnb.x), 0.f);
            v0.y = fmaxf(fmaf(bna.y, v0.y, bnb.y), 0.f);
            v0.z = fmaxf(fmaf(bna.z, v0.z, bnb.z), 0.f);
            v0.w = fmaxf(fmaf(bna.w, v0.w, bnb.w), 0.f);
        }
        acc.x += v0.x; acc.y += v0.y; acc.z += v0.z; acc.w += v0.w;
    }

    red[rl][grp][cg] = acc;
    __syncthreads();

    int col = t6;
    const float* r0 = reinterpret_cast<const float*>(&red[rl][0][col >> 2]);
    const float* r1 = reinterpret_cast<const float*>(&red[rl][1][col >> 2]);
    const float* r2 = reinterpret_cast<const float*>(&red[rl][2][col >> 2]);
    const float* r3 = reinterpret_cast<const float*>(&red[rl][3][col >> 2]);
    int comp = col & 3;
    float s = (r0[comp] + r1[comp]) + (r2[comp] + r3[comp]);
    out[(size_t)r * HDIM + col] = s / (float)g_nnz[r];
}

// ---------------- K3: register-blocked GEMM [16384,64]@[64,64] + bias + BN stats
// 32-row tiles (grid 512, better chip fill), each thread computes a 2x4 block;
// k unrolled by 4 with float4 LDS on both operands.
// MODE==1 applies relu(a*x+b) (previous inner BN) to the input tile.
template <int MODE>
__global__ __launch_bounds__(256) void gemm64(const float* __restrict__ in,
                                              const float* __restrict__ W,
                                              const float* __restrict__ bias,
                                              float* __restrict__ out,
                                              float* __restrict__ part) {
    __shared__ __align__(16) float Ws[64 * 64];      // [k][n]  16KB
    __shared__ __align__(16) float Is[32][72];       // 9KB, 16B-aligned row pad
    __shared__ float redm[16][64];

    int tid = threadIdx.x;
    const float4* W4 = reinterpret_cast<const float4*>(W);
    float4* Ws4 = reinterpret_cast<float4*>(Ws);
    #pragma unroll
    for (int i = tid; i < 1024; i += 256) Ws4[i] = W4[i];

    int row0 = (int)blockIdx.x * 32;
    const float4* in4 = reinterpret_cast<const float4*>(in + (size_t)row0 * HDIM);
    #pragma unroll
    for (int i = tid; i < 512; i += 256) {
        int rr = i >> 4, cg = i & 15;
        float4 v = in4[i];
        if (MODE == 1) {
            float4 a4 = *reinterpret_cast<const float4*>(&g_ab[cg * 4]);
            float4 b4 = *reinterpret_cast<const float4*>(&g_ab[64 + cg * 4]);
            v.x = fmaxf(fmaf(a4.x, v.x, b4.x), 0.f);
            v.y = fmaxf(fmaf(a4.y, v.y, b4.y), 0.f);
            v.z = fmaxf(fmaf(a4.z, v.z, b4.z), 0.f);
            v.w = fmaxf(fmaf(a4.w, v.w, b4.w), 0.f);
        }
        *reinterpret_cast<float4*>(&Is[rr][cg * 4]) = v;
    }
    __syncthreads();

    int ty = tid >> 4;              // row group: rows ty*2, ty*2+1
    int tx = tid & 15;              // col group: cols tx*4..tx*4+3

    float acc[2][4];
    float4 bv = *reinterpret_cast<const float4*>(bias + tx * 4);
    #pragma unroll
    for (int r = 0; r < 2; r++) {
        acc[r][0] = bv.x; acc[r][1] = bv.y; acc[r][2] = bv.z; acc[r][3] = bv.w;
    }

    #pragma unroll
    for (int k = 0; k < 64; k += 4) {
        float4 w0 = *reinterpret_cast<const float4*>(&Ws[(k + 0) * 64 + tx * 4]);
        float4 w1 = *reinterpret_cast<const float4*>(&Ws[(k + 1) * 64 + tx * 4]);
        float4 w2 = *reinterpret_cast<const float4*>(&Ws[(k + 2) * 64 + tx * 4]);
        float4 w3 = *reinterpret_cast<const float4*>(&Ws[(k + 3) * 64 + tx * 4]);
        #pragma unroll
        for (int r = 0; r < 2; r++) {
            float4 iv = *reinterpret_cast<const float4*>(&Is[ty * 2 + r][k]);
            acc[r][0] = fmaf(iv.x, w0.x, acc[r][0]);
            acc[r][1] = fmaf(iv.x, w0.y, acc[r][1]);
            acc[r][2] = fmaf(iv.x, w0.z, acc[r][2]);
            acc[r][3] = fmaf(iv.x, w0.w, acc[r][3]);
            acc[r][0] = fmaf(iv.y, w1.x, acc[r][0]);
            acc[r][1] = fmaf(iv.y, w1.y, acc[r][1]);
            acc[r][2] = fmaf(iv.y, w1.z, acc[r][2]);
            acc[r][3] = fmaf(iv.y, w1.w, acc[r][3]);
            acc[r][0] = fmaf(iv.z, w2.x, acc[r][0]);
            acc[r][1] = fmaf(iv.z, w2.y, acc[r][1]);
            acc[r][2] = fmaf(iv.z, w2.z, acc[r][2]);
            acc[r][3] = fmaf(iv.z, w2.w, acc[r][3]);
            acc[r][0] = fmaf(iv.w, w3.x, acc[r][0]);
            acc[r][1] = fmaf(iv.w, w3.y, acc[r][1]);
            acc[r][2] = fmaf(iv.w, w3.z, acc[r][2]);
            acc[r][3] = fmaf(iv.w, w3.w, acc[r][3]);
        }
    }

    #pragma unroll
    for (int r = 0; r < 2; r++) {
        float4 o = make_float4(acc[r][0], acc[r][1], acc[r][2], acc[r][3]);
        *reinterpret_cast<float4*>(out + (size_t)(row0 + ty * 2 + r) * HDIM + tx * 4) = o;
    }

    // per-block column stats: sum then sumsq
    #pragma unroll
    for (int j = 0; j < 4; j++) redm[ty][tx * 4 + j] = acc[0][j] + acc[1][j];
    __syncthreads();
    if (tid < 64) {
        float v = 0.f;
        #pragma unroll
        for (int i = 0; i < 16; i++) v += redm[i][tid];
        part[(size_t)blockIdx.x * 128 + tid] = v;
    }
    __syncthreads();
    #pragma unroll
    for (int j = 0; j < 4; j++)
        redm[ty][tx * 4 + j] = acc[0][j] * acc[0][j] + acc[1][j] * acc[1][j];
    __syncthreads();
    if (tid < 64) {
        float v = 0.f;
        #pragma unroll
        for (int i = 0; i < 16; i++) v += redm[i][tid];
        part[(size_t)blockIdx.x * 128 + 64 + tid] = v;
    }
}

// ---------------- K4: reduce partials -> BN affine coefficients ----------------
__global__ __launch_bounds__(256) void bn_finalize(const float* __restrict__ g,
                                                   const float* __restrict__ be) {
    int c = blockIdx.x;                      // column 0..63
    int t = threadIdx.x;

    float s = 0.f, q = 0.f;
    #pragma unroll
    for (int b = t; b < NBLK; b += 256) {
        s += g_part[(size_t)b * 128 + c];
        q += g_part[(size_t)b * 128 + 64 + c];
    }
    __shared__ float ss[256];
    __shared__ float qq[256];
    ss[t] = s; qq[t] = q;
    __syncthreads();
    #pragma unroll
    for (int o = 128; o > 0; o >>= 1) {
        if (t < o) { ss[t] += ss[t + o]; qq[t] += qq[t + o]; }
        __syncthreads();
    }
    if (t == 0) {
        const float invn = 1.0f / (float)N_NODES;
        float mean = ss[0] * invn;
        float var  = qq[0] * invn - mean * mean;
        float a = g[c] * rsqrtf(var + BN_EPS);
        g_ab[c]      = a;
        g_ab[64 + c] = be[c] - mean * a;
    }
}

// ---------------- K5: elementwise h = relu(a*t2 + b) (final layer only) ----------------
__global__ __launch_bounds__(256) void apply_bn_relu(const float* __restrict__ t2,
                                                     float* __restrict__ h) {
    int i = blockIdx.x * 256 + threadIdx.x;
    int c = i & 63;
    h[i] = fmaxf(fmaf(g_ab[c], t2[i], g_ab[64 + c]), 0.f);
}

// ---------------- K6: pooled_h = graph_pool @ h  (general dense, zero-skip) ----------------
__global__ __launch_bounds__(256) void pool(const float* __restrict__ gp,
                                            const float* __restrict__ h,
                                            float* __restrict__ out) {
    int g = blockIdx.x;                 // 128 graphs
    int c    = threadIdx.x & 63;
    int lane = threadIdx.x >> 6;        // 4 node-lanes (warp-uniform)
    const float* gprow = gp + (size_t)g * N_NODES;

    float acc = 0.f;
    for (int n0 = lane; n0 < N_NODES; n0 += 32) {
        #pragma unroll
        for (int u = 0; u < 8; u++) {
            int n = n0 + u * 4;
            float w = __ldcs(gprow + n);
            if (w != 0.f) acc = fmaf(w, h[(size_t)n * HDIM + c], acc);
        }
    }
    __shared__ float red[4][64];
    red[lane][c] = acc;
    __syncthreads();
    if (threadIdx.x < 64)
        out[(size_t)g * HDIM + threadIdx.x] =
            (red[0][threadIdx.x] + red[1][threadIdx.x]) +
            (red[2][threadIdx.x] + red[3][threadIdx.x]);
}

// ---------------- launch ----------------
extern "C" void kernel_launch(void* const* d_in, const int* in_sizes, int n_in,
                              void* d_out, int out_size) {
    const float* x   = (const float*)d_in[0];
    const float* adj = (const float*)d_in[1];
    const float* gp  = (const float*)d_in[2];

    const float* P[16];
    for (int i = 0; i < 16; i++) P[i] = (const float*)d_in[3 + i];

    float* out      = (float*)d_out;
    float* h_nodes  = out + 128 * HDIM;   // [16384,64] after the [128,64] readout

    float *pooled, *t, *t2, *part;
    cudaGetSymbolAddress((void**)&pooled, g_pooled);
    cudaGetSymbolAddress((void**)&t,      g_t);
    cudaGetSymbolAddress((void**)&t2,     g_t2);
    cudaGetSymbolAddress((void**)&part,   g_part);

    // 1) fused: adj scan -> CSR + degrees + layer-0 mean aggregation
    scan_agg<<<2048, 256>>>(adj, x, pooled);

    // ---- layer 0 MLP ----
    gemm64<0><<<NBLK, 256>>>(pooled, P[0], P[1], t, part);
    bn_finalize<<<64, 256>>>(P[2], P[3]);               // g1_0, be1_0
    gemm64<1><<<NBLK, 256>>>(t, P[4], P[5], t2, part);
    bn_finalize<<<64, 256>>>(P[6], P[7]);               // g_0, be_0

    // ---- layer 1 (outer BN+ReLU of layer 0 fused into the gather) ----
    agg<1><<<N_NODES / 4, 256>>>(t2, pooled);
    gemm64<0><<<NBLK, 256>>>(pooled, P[8], P[9], t, part);
    bn_finalize<<<64, 256>>>(P[10], P[11]);             // g1_1, be1_1
    gemm64<1><<<NBLK, 256>>>(t, P[12], P[13], t2, part);
    bn_finalize<<<64, 256>>>(P[14], P[15]);             // g_1, be_1
    apply_bn_relu<<<(N_NODES * HDIM) / 256, 256>>>(t2, h_nodes);

    // ---- graph readout ----
    pool<<<128, 256>>>(gp, h_nodes, out);

    (void)in_sizes; (void)n_in; (void)out_size;
}